// round 8
// baseline (speedup 1.0000x reference)
#include <cuda_runtime.h>
#include <cuda_bf16.h>
#include <cstddef>

// Problem constants
constexpr int kNA  = 500000;
constexpr int kNB  = 500000;
constexpr int kE   = 1000000;
constexpr int kHID = 64;
constexpr int kOUT = 32;

// CSR scan geometry: 977 blocks x 512 = 500224 >= 500000 (padded, 512-aligned)
constexpr int SB   = 512;
constexpr int NBLK = 977;
constexpr int PAD  = NBLK * SB;   // 500224

// ---------------- static scratch (allocation-free rule) ----------------
__device__ int g_idx64;                     // 1 if edge indices are int64
__device__ int g_deg[3][PAD];               // per-type dst degree (padded tail stays 0)
__device__ int g_off[3][PAD];               // exclusive prefix (off[500000] == kE via padding)
__device__ int g_cur[3][PAD];               // fill cursors
__device__ int g_bsum[3][NBLK];             // per-block partial sums
__device__ int g_csr[3][kE];                // src indices grouped by dst
__device__ __align__(256) float g_zA_aa[(size_t)kNA * kOUT]; // relu(ha) @ W_rel2[2]
__device__ __align__(256) float g_zA_ab[(size_t)kNA * kOUT]; // relu(ha) @ W_rel2[0]
__device__ __align__(256) float g_zB_ba[(size_t)kNB * kOUT]; // relu(hb) @ W_rel2[1]

// ---------------- packed f32x2 FMA helpers ----------------
__device__ __forceinline__ unsigned long long pack2(float a, float b) {
    unsigned long long r;
    asm("mov.b64 %0, {%1, %2};" : "=l"(r) : "f"(a), "f"(b));
    return r;
}
__device__ __forceinline__ void fma2(unsigned long long& d, unsigned long long a, unsigned long long b) {
    asm("fma.rn.f32x2 %0, %1, %2, %0;" : "+l"(d) : "l"(a), "l"(b));
}

// ---------------- phase 0: zero accumulators + index-width detection ----------------
// jnp int64 silently downcasts to int32 when jax x64 is off; detect actual layout:
// for little-endian int64 values < 2^31, every odd 32-bit word is zero.
// g_idx64 is written here and first consumed by hist_kernel (next launch) -> ordered.
__global__ void zero_kernel(const int* __restrict__ ei_words) {
    int i = blockIdx.x * blockDim.x + threadIdx.x;
    if (i < 3 * PAD) (&g_deg[0][0])[i] = 0;
    if (i == 0) {
        int nz = 0;
        for (int q = 0; q < 64; ++q) nz |= __ldg(&ei_words[2 * q + 1]);
        g_idx64 = (nz == 0) ? 1 : 0;
    }
}

__device__ __forceinline__ void load_edge(const int* __restrict__ ei, int e, int& src, int& dst) {
    if (g_idx64) {
        src = __ldg(&ei[2 * e]);
        dst = __ldg(&ei[2 * kE + 2 * e]);
    } else {
        src = __ldg(&ei[e]);
        dst = __ldg(&ei[kE + e]);
    }
}
__device__ __forceinline__ int load_dst(const int* __restrict__ ei, int e) {
    return g_idx64 ? __ldg(&ei[2 * kE + 2 * e]) : __ldg(&ei[kE + e]);
}

// ---------------- CSR build ----------------
__global__ void hist_kernel(const int* __restrict__ e0, const int* __restrict__ e1,
                            const int* __restrict__ e2) {
    int t = blockIdx.x * blockDim.x + threadIdx.x;
    if (t >= 3 * kE) return;
    int type = t / kE;
    int e = t - type * kE;
    const int* ei = (type == 0) ? e0 : (type == 1) ? e1 : e2;
    int d = load_dst(ei, e);
    atomicAdd(&g_deg[type][d], 1);
}

// Block-level Hillis-Steele exclusive scan (512 per block)
__global__ void scan1_kernel() {
    __shared__ int s[SB];
    int b = blockIdx.x;                 // 0 .. 3*NBLK-1
    int type = b / NBLK;
    int blk = b - type * NBLK;
    int tid = threadIdx.x;
    int i = blk * SB + tid;             // always < PAD
    int v = g_deg[type][i];
    s[tid] = v;
    __syncthreads();
    #pragma unroll
    for (int d = 1; d < SB; d <<= 1) {
        int t2 = (tid >= d) ? s[tid - d] : 0;
        __syncthreads();
        s[tid] += t2;
        __syncthreads();
    }
    g_off[type][i] = s[tid] - v;        // exclusive
    if (tid == SB - 1) g_bsum[type][blk] = s[SB - 1];
}

// One block per edge type scans its NBLK partial sums
__global__ void scan2_kernel() {
    __shared__ int s[1024];
    int type = blockIdx.x;
    int tid = threadIdx.x;
    int v = (tid < NBLK) ? g_bsum[type][tid] : 0;
    s[tid] = v;
    __syncthreads();
    #pragma unroll
    for (int d = 1; d < 1024; d <<= 1) {
        int t2 = (tid >= d) ? s[tid - d] : 0;
        __syncthreads();
        s[tid] += t2;
        __syncthreads();
    }
    if (tid < NBLK) g_bsum[type][tid] = s[tid] - v;   // exclusive block offsets
}

__global__ void scan3_kernel() {
    int t = blockIdx.x * blockDim.x + threadIdx.x;
    if (t >= 3 * PAD) return;
    int type = t / PAD;
    int i = t - type * PAD;
    int o = g_off[type][i] + g_bsum[type][i >> 9];    // i/SB
    g_off[type][i] = o;
    g_cur[type][i] = o;
}

__global__ void fill_kernel(const int* __restrict__ e0, const int* __restrict__ e1,
                            const int* __restrict__ e2) {
    int t = blockIdx.x * blockDim.x + threadIdx.x;
    if (t >= 3 * kE) return;
    int type = t / kE;
    int e = t - type * kE;
    const int* ei = (type == 0) ? e0 : (type == 1) ? e1 : e2;
    int src, dst;
    load_edge(ei, e, src, dst);
    int pos = atomicAdd(&g_cur[type][dst], 1);
    g_csr[type][pos] = src;
}

// ---------------- CSR scalar gather with 2-deep pipeline ----------------
__device__ __forceinline__ float csr_sum_scalar(const int* __restrict__ csr,
                                                const float* __restrict__ x,
                                                int e0, int e1) {
    float s = 0.f;
    int n = e1 - e0;
    if (n <= 0) return s;
    int idx0 = __ldg(&csr[e0]);
    #pragma unroll 1
    for (int k = 1; k < n; ++k) {
        int idx1 = __ldg(&csr[e0 + k]);   // prefetch next index
        s += __ldg(&x[idx0]);
        idx0 = idx1;
    }
    s += __ldg(&x[idx0]);
    return s;
}

// ---------------- fused per-node kernels (layer-1 gather + both MLP layers) ----------------
// a-nodes: ha[j] = relu(s_ba*Wr1[1][j] + s_aa*Wr1[2][j] + x_a*(Wo1[1][j]+Wo1[2][j]) + b1[1][j]+b1[2][j])
// cols 0-31 = W_rel2[2] (->zA_aa), 32-63 = W_rel2[0] (->zA_ab), 64-95 = W_root2[1]+W_root2[2] (+bias -> out)
__global__ void __launch_bounds__(256) node_a_kernel(
    const float* __restrict__ x_a, const float* __restrict__ x_b,
    const float* __restrict__ W_rel1, const float* __restrict__ W_root1, const float* __restrict__ b1,
    const float* __restrict__ W_rel2, const float* __restrict__ W_root2, const float* __restrict__ b2,
    float* __restrict__ out) {
    __shared__ __align__(16) float4 sL1[kHID];
    __shared__ __align__(16) float  sWc[kHID * 96];
    __shared__ float sBias[kOUT];

    int tid = threadIdx.x;
    for (int j = tid; j < kHID; j += blockDim.x) {
        sL1[j] = make_float4(W_rel1[1 * kHID + j], W_rel1[2 * kHID + j],
                             W_root1[1 * kHID + j] + W_root1[2 * kHID + j],
                             b1[kHID + j] + b1[2 * kHID + j]);
    }
    for (int idx = tid; idx < kHID * 96; idx += blockDim.x) {
        int j = idx / 96, k = idx % 96;
        float v;
        if (k < 32)      v = W_rel2[2 * 2048 + j * 32 + k];
        else if (k < 64) v = W_rel2[0 * 2048 + j * 32 + (k - 32)];
        else             v = W_root2[1 * 2048 + j * 32 + (k - 64)] +
                             W_root2[2 * 2048 + j * 32 + (k - 64)];
        sWc[idx] = v;
    }
    if (tid < kOUT) sBias[tid] = b2[kOUT + tid] + b2[2 * kOUT + tid];
    __syncthreads();

    int i = blockIdx.x * blockDim.x + tid;
    if (i >= kNA) return;

    // layer-1 scalar aggregation via CSR gather (no atomics); issue both range
    // loads up front so the two loops' memory latencies overlap.
    float xa = x_a[i];
    int ba0 = g_off[1][i], ba1 = g_off[1][i + 1];
    int aa0 = g_off[2][i], aa1 = g_off[2][i + 1];
    float sba = csr_sum_scalar(g_csr[1], x_b, ba0, ba1);
    float saa = csr_sum_scalar(g_csr[2], x_a, aa0, aa1);

    #pragma unroll 1
    for (int pass = 0; pass < 3; ++pass) {
        unsigned long long acc[16];
        if (pass == 2) {
            #pragma unroll
            for (int m = 0; m < 16; ++m) acc[m] = pack2(sBias[2 * m], sBias[2 * m + 1]);
        } else {
            #pragma unroll
            for (int m = 0; m < 16; ++m) acc[m] = 0ULL;
        }
        const ulonglong2* Wp = reinterpret_cast<const ulonglong2*>(sWc) + pass * 8;
        #pragma unroll 8
        for (int j = 0; j < kHID; ++j) {
            float4 w = sL1[j];
            float h = fmaxf(fmaf(sba, w.x, fmaf(saa, w.y, fmaf(xa, w.z, w.w))), 0.f);
            unsigned long long hp = pack2(h, h);
            const ulonglong2* Wr = Wp + j * 24;   // row stride: 96 floats = 24 ulonglong2
            #pragma unroll
            for (int q = 0; q < 8; ++q) {
                ulonglong2 wv = Wr[q];
                fma2(acc[2 * q],     hp, wv.x);
                fma2(acc[2 * q + 1], hp, wv.y);
            }
        }
        float* dstf = (pass == 0) ? (g_zA_aa + (size_t)i * kOUT)
                    : (pass == 1) ? (g_zA_ab + (size_t)i * kOUT)
                                  : (out + (size_t)i * kOUT);
        ulonglong2* dst = reinterpret_cast<ulonglong2*>(dstf);
        #pragma unroll
        for (int q = 0; q < 8; ++q) dst[q] = make_ulonglong2(acc[2 * q], acc[2 * q + 1]);
    }
}

// b-nodes: hb[j] = relu(s_ab*Wr1[0][j] + x_b*Wo1[0][j] + b1[0][j])
// cols 0-31 = W_rel2[1] (->zB_ba), 32-63 = W_root2[0] (+b2[0] -> out rows [NA, NA+NB))
__global__ void __launch_bounds__(256) node_b_kernel(
    const float* __restrict__ x_a, const float* __restrict__ x_b,
    const float* __restrict__ W_rel1, const float* __restrict__ W_root1, const float* __restrict__ b1,
    const float* __restrict__ W_rel2, const float* __restrict__ W_root2, const float* __restrict__ b2,
    float* __restrict__ out) {
    __shared__ __align__(16) float4 sL1[kHID];
    __shared__ __align__(16) float  sWc[kHID * 64];
    __shared__ float sBias[kOUT];

    int tid = threadIdx.x;
    for (int j = tid; j < kHID; j += blockDim.x) {
        sL1[j] = make_float4(W_rel1[j], W_root1[j], b1[j], 0.f);
    }
    for (int idx = tid; idx < kHID * 64; idx += blockDim.x) {
        int j = idx / 64, k = idx % 64;
        float v;
        if (k < 32) v = W_rel2[1 * 2048 + j * 32 + k];
        else        v = W_root2[0 * 2048 + j * 32 + (k - 32)];
        sWc[idx] = v;
    }
    if (tid < kOUT) sBias[tid] = b2[tid];
    __syncthreads();

    int i = blockIdx.x * blockDim.x + tid;
    if (i >= kNB) return;

    float xb = x_b[i];
    int ab0 = g_off[0][i], ab1 = g_off[0][i + 1];
    float sab = csr_sum_scalar(g_csr[0], x_a, ab0, ab1);

    #pragma unroll 1
    for (int pass = 0; pass < 2; ++pass) {
        unsigned long long acc[16];
        if (pass == 1) {
            #pragma unroll
            for (int m = 0; m < 16; ++m) acc[m] = pack2(sBias[2 * m], sBias[2 * m + 1]);
        } else {
            #pragma unroll
            for (int m = 0; m < 16; ++m) acc[m] = 0ULL;
        }
        const ulonglong2* Wp = reinterpret_cast<const ulonglong2*>(sWc) + pass * 8;
        #pragma unroll 8
        for (int j = 0; j < kHID; ++j) {
            float4 w = sL1[j];
            float h = fmaxf(fmaf(sab, w.x, fmaf(xb, w.y, w.z)), 0.f);
            unsigned long long hp = pack2(h, h);
            const ulonglong2* Wr = Wp + j * 16;   // row stride: 64 floats = 16 ulonglong2
            #pragma unroll
            for (int q = 0; q < 8; ++q) {
                ulonglong2 wv = Wr[q];
                fma2(acc[2 * q],     hp, wv.x);
                fma2(acc[2 * q + 1], hp, wv.y);
            }
        }
        float* dstf = (pass == 0) ? (g_zB_ba + (size_t)i * kOUT)
                                  : (out + ((size_t)kNA + i) * kOUT);
        ulonglong2* dst = reinterpret_cast<ulonglong2*>(dstf);
        #pragma unroll
        for (int q = 0; q < 8; ++q) dst[q] = make_ulonglong2(acc[2 * q], acc[2 * q + 1]);
    }
}

// ---------------- layer-2 aggregation: atomic-free CSR gather ----------------
// 8 lanes per destination row; lane c owns float4 chunk c. out already holds the
// root+bias contribution (written by node kernels) -> read, accumulate, write.
__global__ void __launch_bounds__(256) gather_out_kernel(float* __restrict__ out) {
    int t = blockIdx.x * blockDim.x + threadIdx.x;
    int i = t >> 3;
    if (i >= kNA + kNB) return;
    int c = t & 7;

    float4* orow = reinterpret_cast<float4*>(out + (size_t)i * kOUT);
    float4 acc = orow[c];

    if (i < kNA) {
        const float4* zb = reinterpret_cast<const float4*>(g_zB_ba);
        const float4* za = reinterpret_cast<const float4*>(g_zA_aa);
        int e0 = g_off[1][i], e1 = g_off[1][i + 1];
        int f0 = g_off[2][i], f1 = g_off[2][i + 1];
        #pragma unroll 1
        for (int e = e0; e < e1; ++e) {
            float4 v = __ldg(&zb[(size_t)g_csr[1][e] * 8 + c]);
            acc.x += v.x; acc.y += v.y; acc.z += v.z; acc.w += v.w;
        }
        #pragma unroll 1
        for (int e = f0; e < f1; ++e) {
            float4 v = __ldg(&za[(size_t)g_csr[2][e] * 8 + c]);
            acc.x += v.x; acc.y += v.y; acc.z += v.z; acc.w += v.w;
        }
    } else {
        int ib = i - kNA;
        const float4* zab = reinterpret_cast<const float4*>(g_zA_ab);
        int e0 = g_off[0][ib], e1 = g_off[0][ib + 1];
        #pragma unroll 1
        for (int e = e0; e < e1; ++e) {
            float4 v = __ldg(&zab[(size_t)g_csr[0][e] * 8 + c]);
            acc.x += v.x; acc.y += v.y; acc.z += v.z; acc.w += v.w;
        }
    }
    orow[c] = acc;
}

// ---------------- launch ----------------
extern "C" void kernel_launch(void* const* d_in, const int* in_sizes, int n_in,
                              void* d_out, int out_size) {
    const float* x_a     = (const float*)d_in[0];
    const float* x_b     = (const float*)d_in[1];
    const int*   ei_ab   = (const int*)d_in[2];   // width handled at runtime
    const int*   ei_ba   = (const int*)d_in[3];
    const int*   ei_aa   = (const int*)d_in[4];
    const float* W_rel1  = (const float*)d_in[5];
    const float* W_root1 = (const float*)d_in[6];
    const float* b1      = (const float*)d_in[7];
    const float* W_rel2  = (const float*)d_in[8];
    const float* W_root2 = (const float*)d_in[9];
    const float* b2      = (const float*)d_in[10];
    float* out = (float*)d_out;

    zero_kernel<<<(3 * PAD + 255) / 256, 256>>>(ei_ab);
    hist_kernel<<<(3 * kE + 255) / 256, 256>>>(ei_ab, ei_ba, ei_aa);
    scan1_kernel<<<3 * NBLK, SB>>>();
    scan2_kernel<<<3, 1024>>>();
    scan3_kernel<<<(3 * PAD + 255) / 256, 256>>>();
    fill_kernel<<<(3 * kE + 255) / 256, 256>>>(ei_ab, ei_ba, ei_aa);
    node_a_kernel<<<(kNA + 255) / 256, 256>>>(x_a, x_b, W_rel1, W_root1, b1, W_rel2, W_root2, b2, out);
    node_b_kernel<<<(kNB + 255) / 256, 256>>>(x_a, x_b, W_rel1, W_root1, b1, W_rel2, W_root2, b2, out);
    gather_out_kernel<<<((kNA + kNB) * 8 + 255) / 256, 256>>>(out);
}